// round 7
// baseline (speedup 1.0000x reference)
#include <cuda_runtime.h>
#include <cuda_bf16.h>
#include <math.h>
#include <stdint.h>

#define BATCH   128
#define SEQ     512
#define INPUT   512
#define HIDDEN  1024
#define OUTPUT  256
#define NBLK    128
#define JW      32
#define MW      32

// ---------------- device scratch (no allocs allowed) ----------------
__device__ float          g_xin[(size_t)SEQ * BATCH * HIDDEN];   // [s][b][h]
__device__ float          g_hf[2][BATCH * HIDDEN];
__device__ __nv_bfloat16  g_hhi[2][BATCH * HIDDEN];
__device__ __nv_bfloat16  g_hlo[2][BATCH * HIDDEN];
__device__ __nv_bfloat16  g_xhi[(size_t)BATCH * SEQ * INPUT];
__device__ __nv_bfloat16  g_xlo[(size_t)BATCH * SEQ * INPUT];
__device__ __nv_bfloat16  g_wThi[HIDDEN * INPUT];
__device__ __nv_bfloat16  g_wTlo[HIDDEN * INPUT];
__device__ unsigned g_arrive[NBLK * 32];    // 128B-strided arrival flags
__device__ unsigned g_bar_gen;

// ---------------- scan smem layout ----------------
#define OFF_WHI    0                 // [kblk16][n32][128B] 64 KB
#define OFF_WLO    65536             // 64 KB
#define OFF_STAGE  131072            // 3 slots x 32 KB (4 kg x (hi4K+lo4K))
#define OFF_RED    OFF_STAGE         // 12 KB reduction scratch (reuses slot 0)
#define OFF_BH     229376
#define OFF_ITAU   229504
#define OFF_GEN0   229632
#define SCAN_SMEM  229696

// ---------------- gemm smem layout ----------------
#define OFF_GA     0
#define OFF_GB     98304
#define OFF_BIN    147456
#define GEMM_SMEM  147968

__device__ __forceinline__ uint32_t smem_u32(const void* p) {
    uint32_t a;
    asm("{ .reg .u64 t; cvta.to.shared.u64 t, %1; cvt.u32.u64 %0, t; }" : "=r"(a) : "l"(p));
    return a;
}
#define CP_COMMIT() asm volatile("cp.async.commit_group;" ::: "memory")
#define CP_WAIT1()  asm volatile("cp.async.wait_group 1;" ::: "memory")
#define CP_WAIT0()  asm volatile("cp.async.wait_group 0;" ::: "memory")

__device__ __forceinline__ void cp16(uint32_t dst, const void* src) {
    asm volatile("cp.async.cg.shared.global [%0], [%1], 16;" :: "r"(dst), "l"(src) : "memory");
}
__device__ __forceinline__ void ldsm4(uint32_t& r0, uint32_t& r1, uint32_t& r2, uint32_t& r3,
                                      uint32_t a) {
    asm volatile("ldmatrix.sync.aligned.m8n8.x4.shared.b16 {%0,%1,%2,%3}, [%4];"
                 : "=r"(r0), "=r"(r1), "=r"(r2), "=r"(r3) : "r"(a));
}
__device__ __forceinline__ void mma16816(float* d, const uint32_t* a, uint32_t b0, uint32_t b1) {
    asm volatile("mma.sync.aligned.m16n8k16.row.col.f32.bf16.bf16.f32 "
                 "{%0,%1,%2,%3}, {%4,%5,%6,%7}, {%8,%9}, {%0,%1,%2,%3};"
                 : "+f"(d[0]), "+f"(d[1]), "+f"(d[2]), "+f"(d[3])
                 : "r"(a[0]), "r"(a[1]), "r"(a[2]), "r"(a[3]), "r"(b0), "r"(b1));
}

// ---- flag-array grid barrier: parallel arrivals, block0 gathers & releases ----
__device__ __forceinline__ void bar_arrive(unsigned target)
{
    __syncthreads();
    if (threadIdx.x == 0) {
        __threadfence();
        atomicExch(&g_arrive[blockIdx.x * 32], target);
    }
}
__device__ __forceinline__ void bar_wait(unsigned target)
{
    if (blockIdx.x == 0) {
        if (threadIdx.x < NBLK) {
            while ((int)(*(volatile unsigned*)&g_arrive[threadIdx.x * 32] - target) < 0) { }
        }
        __syncthreads();
        if (threadIdx.x == 0) {
            __threadfence();
            atomicExch(&g_bar_gen, target);
        }
    }
    if (threadIdx.x == 0) {
        while ((int)(*(volatile unsigned*)&g_bar_gen - target) < 0) { }
        __threadfence();
    }
    __syncthreads();
}

__device__ __forceinline__ uint32_t pbf2(float a, float b) {
    __nv_bfloat162 t = __floats2bfloat162_rn(a, b);
    return *(uint32_t*)&t;
}

// ---------------------------------------------------------------------------
// Conversion kernels: fp32 -> bf16 hi/lo planes
// ---------------------------------------------------------------------------
__global__ __launch_bounds__(256) void conv_x_kernel(const float* __restrict__ x)
{
    const size_t total = (size_t)BATCH * SEQ * INPUT / 2;
    size_t base = (size_t)blockIdx.x * 256 + threadIdx.x;
    size_t stride = (size_t)gridDim.x * 256;
    uint32_t* xhi = (uint32_t*)g_xhi;
    uint32_t* xlo = (uint32_t*)g_xlo;
    for (size_t p = base; p < total; p += stride) {
        float2 v = ((const float2*)x)[p];
        uint32_t hp = pbf2(v.x, v.y);
        __nv_bfloat162 hb = *(__nv_bfloat162*)&hp;
        xhi[p] = hp;
        xlo[p] = pbf2(v.x - __bfloat162float(hb.x), v.y - __bfloat162float(hb.y));
    }
}

__global__ __launch_bounds__(256) void conv_w_kernel(const float* __restrict__ Win)
{
    int idx = blockIdx.x * 256 + threadIdx.x;
    if (idx >= INPUT * HIDDEN) return;
    int k = idx >> 10, n = idx & 1023;
    float w = Win[idx];
    __nv_bfloat16 whi = __float2bfloat16(w);
    g_wThi[(size_t)n * INPUT + k] = whi;
    g_wTlo[(size_t)n * INPUT + k] = __float2bfloat16(w - __bfloat162float(whi));
}

// ---------------------------------------------------------------------------
// Phase 1: xin = x @ W_in + b_in  (bf16x3 mma). Block: M=128, N=64, K=512.
// ---------------------------------------------------------------------------
__device__ __forceinline__ void gstage(uint32_t sb, int kc, int m0, int n0, int tid)
{
    uint32_t abase = sb + OFF_GA + (uint32_t)(kc % 3) * 32768u;
    uint32_t bbase = sb + OFF_GB + (uint32_t)(kc % 3) * 16384u;
#pragma unroll
    for (int u = 0; u < 8; ++u) {
        int g = tid + u * 256;
        int seg = g & 7, row = (g >> 3) & 127, plane = g >> 10;
        const char* src = (const char*)(plane ? g_xlo : g_xhi)
                        + (size_t)(m0 + row) * 1024 + (size_t)kc * 128 + seg * 16;
        uint32_t dst = abase + plane * 16384 + row * 128 + ((seg * 16) ^ ((row & 7) << 4));
        cp16(dst, src);
    }
#pragma unroll
    for (int u = 0; u < 4; ++u) {
        int g = tid + u * 256;
        int seg = g & 7, row = (g >> 3) & 63, plane = g >> 9;
        const char* src = (const char*)(plane ? g_wTlo : g_wThi)
                        + (size_t)(n0 + row) * 1024 + (size_t)kc * 128 + seg * 16;
        uint32_t dst = bbase + plane * 8192 + row * 128 + ((seg * 16) ^ ((row & 7) << 4));
        cp16(dst, src);
    }
}

__global__ __launch_bounds__(256, 1) void gemm_xin_mma(const float* __restrict__ bin)
{
    extern __shared__ __align__(1024) char smem[];
    const uint32_t sb = smem_u32(smem);
    const int tid = threadIdx.x, wid = tid >> 5, lid = tid & 31;
    const int n0 = blockIdx.x * 64, m0 = blockIdx.y * 128;
    const int mq = wid & 3, nh = wid >> 2;
    float* bin_s = (float*)(smem + OFF_BIN);
    if (tid < 16) ((float4*)bin_s)[tid] = ((const float4*)(bin + n0))[tid];

    const int grp = lid >> 3;
    int a_rowl[2];
    a_rowl[0] = mq * 32 + (lid & 7) + ((grp & 1) << 3);
    a_rowl[1] = a_rowl[0] + 16;
    const int a_koff = (grp >> 1) << 4;
    const int b_nr   = nh * 32 + (lid & 7) + ((grp >> 1) << 3);
    const int b_koff = (grp & 1) << 4;
    const uint32_t b_xor = (uint32_t)((b_nr & 7) << 4);

    float acc[2][4][4];
#pragma unroll
    for (int i = 0; i < 2; ++i)
#pragma unroll
        for (int j = 0; j < 4; ++j)
#pragma unroll
            for (int r = 0; r < 4; ++r) acc[i][j][r] = 0.0f;

    gstage(sb, 0, m0, n0, tid); CP_COMMIT();
    gstage(sb, 1, m0, n0, tid); CP_COMMIT();

    for (int kc = 0; kc < 8; ++kc) {
        CP_WAIT1();
        __syncthreads();
        if (kc + 2 < 8) gstage(sb, kc + 2, m0, n0, tid);
        CP_COMMIT();
        const uint32_t abase = sb + OFF_GA + (uint32_t)(kc % 3) * 32768u;
        const uint32_t bbase = sb + OFF_GB + (uint32_t)(kc % 3) * 16384u;
#pragma unroll
        for (int k2 = 0; k2 < 4; ++k2) {
            const uint32_t kb = (uint32_t)(k2 * 32);
            uint32_t ahi[2][4], alo[2][4];
#pragma unroll
            for (int mt = 0; mt < 2; ++mt) {
                uint32_t aa = abase + (uint32_t)(a_rowl[mt] * 128)
                            + ((kb + a_koff) ^ ((a_rowl[mt] & 7) << 4));
                ldsm4(ahi[mt][0], ahi[mt][1], ahi[mt][2], ahi[mt][3], aa);
                ldsm4(alo[mt][0], alo[mt][1], alo[mt][2], alo[mt][3], aa + 16384);
            }
            uint32_t bhi[8], blo[8];
            {
                uint32_t ba = bbase + (uint32_t)(b_nr * 128) + ((kb + b_koff) ^ b_xor);
                ldsm4(bhi[0], bhi[1], bhi[2], bhi[3], ba);
                ldsm4(bhi[4], bhi[5], bhi[6], bhi[7], ba + 2048);
                ldsm4(blo[0], blo[1], blo[2], blo[3], ba + 8192);
                ldsm4(blo[4], blo[5], blo[6], blo[7], ba + 8192 + 2048);
            }
#pragma unroll
            for (int mt = 0; mt < 2; ++mt)
#pragma unroll
                for (int j = 0; j < 4; ++j) {
                    mma16816(acc[mt][j], ahi[mt], bhi[j * 2], bhi[j * 2 + 1]);
                    mma16816(acc[mt][j], alo[mt], bhi[j * 2], bhi[j * 2 + 1]);
                    mma16816(acc[mt][j], ahi[mt], blo[j * 2], blo[j * 2 + 1]);
                }
        }
    }

    const int er = lid >> 2, ec = (lid & 3) * 2;
#pragma unroll
    for (int mt = 0; mt < 2; ++mt)
#pragma unroll
        for (int rt = 0; rt < 2; ++rt) {
            int m = m0 + mq * 32 + mt * 16 + er + rt * 8;
            int b = m >> 9, s = m & 511;
            float* orow = g_xin + ((size_t)s * BATCH + b) * HIDDEN + n0;
#pragma unroll
            for (int j = 0; j < 4; ++j) {
                int nl = nh * 32 + j * 8 + ec;
                float2 v;
                v.x = acc[mt][j][rt * 2 + 0] + bin_s[nl];
                v.y = acc[mt][j][rt * 2 + 1] + bin_s[nl + 1];
                *(float2*)(orow + nl) = v;
            }
        }
}

// ---------------------------------------------------------------------------
// Scan: 128 blocks x 512 threads. 16 warps = 2m x 2n x 4k.
// Slot (32KB): kg in 0..3 at kg*8192: hi [32row][128B] + lo at +4096.
// Iteration i stages chunks {i, 4+i, 8+i, 12+i} (chunk c = kg*4 + i).
// ---------------------------------------------------------------------------
__device__ __forceinline__ void stage_quad(uint32_t sb, const __nv_bfloat16* hi,
                                           const __nv_bfloat16* lo, int i, int m0, int tid)
{
    uint32_t base = sb + OFF_STAGE + (uint32_t)(i % 3) * 32768u;
#pragma unroll
    for (int u = 0; u < 4; ++u) {
        int g = tid + u * 512;                 // seg(8) x row(32) x plane(2) x kg(4)
        int seg = g & 7, row = (g >> 3) & 31, plane = (g >> 8) & 1, kg = g >> 9;
        int c = kg * 4 + i;
        const char* src = (const char*)(plane ? lo : hi)
                        + (size_t)(m0 + row) * 2048 + (size_t)c * 128 + seg * 16;
        uint32_t dst = base + kg * 8192 + plane * 4096 + row * 128
                     + ((seg * 16) ^ ((row & 7) << 4));
        cp16(dst, src);
    }
}

__global__ __launch_bounds__(512, 1) void scan_mma_kernel(
    const float* __restrict__ Wh,  const float* __restrict__ bh,
    const float* __restrict__ tau, const float* __restrict__ Wout,
    const float* __restrict__ bout, float* __restrict__ out)
{
    extern __shared__ __align__(1024) char smem[];
    const uint32_t sb = smem_u32(smem);
    const int tid = threadIdx.x, wid = tid >> 5, lid = tid & 31;
    const int jt = blockIdx.x >> 2, mt_blk = blockIdx.x & 3;
    const int j0 = jt * JW, m0 = mt_blk * MW;
    float* bh_s   = (float*)(smem + OFF_BH);
    float* itau_s = (float*)(smem + OFF_ITAU);
    float* red    = (float*)(smem + OFF_RED);

    if (tid == 0) *(unsigned*)(smem + OFF_GEN0) = *(volatile unsigned*)&g_bar_gen;
    if (tid < JW) {
        bh_s[tid]   = bh[j0 + tid];
        itau_s[tid] = 1.0f / tau[j0 + tid];
    }

    // W slice -> SMEM bf16 hi/lo, [kblk16][n32][128B] swizzled
    for (int idx = tid; idx < 1024 * 8; idx += 512) {
        int k = idx >> 3, nq = idx & 7;
        float4 wv = *(const float4*)(Wh + (size_t)k * HIDDEN + j0 + nq * 4);
        float w[4] = {wv.x, wv.y, wv.z, wv.w};
#pragma unroll
        for (int e = 0; e < 4; ++e) {
            int n = nq * 4 + e;
            uint32_t so = (uint32_t)((k >> 6) * 4096 + n * 128)
                        + (uint32_t)((((k & 63) * 2) ^ ((n & 7) << 4)));
            __nv_bfloat16 whi = __float2bfloat16(w[e]);
            *(__nv_bfloat16*)(smem + OFF_WHI + so) = whi;
            *(__nv_bfloat16*)(smem + OFF_WLO + so) =
                __float2bfloat16(w[e] - __bfloat162float(whi));
        }
    }

    // zero own h plane patch
    for (int idx = tid; idx < MW * JW / 2; idx += 512) {
        int r = idx / (JW / 2), c = idx % (JW / 2);
        size_t o = (size_t)(m0 + r) * HIDDEN + j0 + c * 2;
        *(uint32_t*)(g_hhi[0] + o) = 0u;
        *(uint32_t*)(g_hlo[0] + o) = 0u;
    }
    __syncthreads();
    const unsigned gen0 = *(unsigned*)(smem + OFF_GEN0);

    unsigned nbar = 0;
    ++nbar; bar_arrive(gen0 + nbar); bar_wait(gen0 + nbar);

    // warp roles: 2m x 2n x 4k
    const int w_mt = wid & 1, w_nh = (wid >> 1) & 1, kg = wid >> 2;
    const int grp = lid >> 3;
    const int a_row  = w_mt * 16 + (lid & 7) + ((grp & 1) << 3);
    const int a_koff = (grp >> 1) << 4;
    const uint32_t a_off = (uint32_t)(a_row * 128);
    const uint32_t a_xor = (uint32_t)((a_row & 7) << 4);
    const int b_nr   = w_nh * 16 + (lid & 7) + ((grp >> 1) << 3);
    const int b_koff = (grp & 1) << 4;
    const uint32_t b_xor = (uint32_t)((b_nr & 7) << 4);
    const int er = lid >> 2, ec = (lid & 3) * 2;
    const int q = w_mt * 2 + w_nh;

    // registers: carried h (kg0 only) + prefetched xin
    float2 hreg[2][2], xv[2][2];
#pragma unroll
    for (int rt = 0; rt < 2; ++rt)
#pragma unroll
        for (int j = 0; j < 2; ++j) hreg[rt][j] = make_float2(0.f, 0.f);
    if (kg == 0) {
#pragma unroll
        for (int rt = 0; rt < 2; ++rt) {
            int row = m0 + w_mt * 16 + er + rt * 8;
            const float* xp = g_xin + (size_t)row * HIDDEN + j0;   // t = 0
#pragma unroll
            for (int j = 0; j < 2; ++j)
                xv[rt][j] = *(const float2*)(xp + w_nh * 16 + j * 8 + ec);
        }
    }

    int cur = 0;
    for (int t = 0; t < SEQ; ++t) {
        const __nv_bfloat16* hhi = g_hhi[cur];
        const __nv_bfloat16* hlo = g_hlo[cur];

        float acc[2][4];
#pragma unroll
        for (int j = 0; j < 2; ++j)
#pragma unroll
            for (int r = 0; r < 4; ++r) acc[j][r] = 0.0f;

        stage_quad(sb, hhi, hlo, 0, m0, tid); CP_COMMIT();
        stage_quad(sb, hhi, hlo, 1, m0, tid); CP_COMMIT();

        for (int i = 0; i < 4; ++i) {
            CP_WAIT1();
            __syncthreads();
            if (i + 2 < 4) stage_quad(sb, hhi, hlo, i + 2, m0, tid);
            CP_COMMIT();

            const uint32_t abase = sb + OFF_STAGE + (uint32_t)(i % 3) * 32768u
                                 + (uint32_t)(kg * 8192);
            const int c = kg * 4 + i;
            const uint32_t wbase = sb + OFF_WHI + (uint32_t)(c * 4096);
#pragma unroll
            for (int k2 = 0; k2 < 4; ++k2) {
                const uint32_t kb = (uint32_t)(k2 * 32);
                uint32_t ahi[4], alo[4];
                uint32_t aa = abase + a_off + ((kb + a_koff) ^ a_xor);
                ldsm4(ahi[0], ahi[1], ahi[2], ahi[3], aa);
                ldsm4(alo[0], alo[1], alo[2], alo[3], aa + 4096);
                uint32_t bhi[4], blo[4];
                uint32_t ba = wbase + (uint32_t)(b_nr * 128) + ((kb + b_koff) ^ b_xor);
                ldsm4(bhi[0], bhi[1], bhi[2], bhi[3], ba);
                ldsm4(blo[0], blo[1], blo[2], blo[3], ba + (OFF_WLO - OFF_WHI));
#pragma unroll
                for (int j = 0; j < 2; ++j) {
                    mma16816(acc[j], ahi, bhi[j * 2], bhi[j * 2 + 1]);
                    mma16816(acc[j], alo, bhi[j * 2], bhi[j * 2 + 1]);
                    mma16816(acc[j], ahi, blo[j * 2], blo[j * 2 + 1]);
                }
            }
        }
        CP_WAIT0();
        __syncthreads();                      // all compute on slot 0 done

        // k-reduction: kg 1..3 publish partials into slot-0 scratch
        if (kg != 0) {
#pragma unroll
            for (int rt = 0; rt < 2; ++rt)
#pragma unroll
                for (int j = 0; j < 2; ++j)
                    *(float2*)&red[((kg - 1) * 4 + q) * 256 + (rt * 8 + er) * 16 + j * 8 + ec]
                        = make_float2(acc[j][rt * 2], acc[j][rt * 2 + 1]);
        }
        __syncthreads();

        if (kg == 0) {
            uint32_t* hhn = (uint32_t*)g_hhi[cur ^ 1];
            uint32_t* hln = (uint32_t*)g_hlo[cur ^ 1];
#pragma unroll
            for (int rt = 0; rt < 2; ++rt) {
                int row = m0 + w_mt * 16 + er + rt * 8;
                size_t rb = (size_t)row * HIDDEN + j0;
#pragma unroll
                for (int j = 0; j < 2; ++j) {
                    int nl = w_nh * 16 + j * 8 + ec;
                    float z0 = acc[j][rt * 2 + 0] + xv[rt][j].x + bh_s[nl];
                    float z1 = acc[j][rt * 2 + 1] + xv[rt][j].y + bh_s[nl + 1];
#pragma unroll
                    for (int p = 0; p < 3; ++p) {
                        float2 pp = *(float2*)&red[(p * 4 + q) * 256
                                                   + (rt * 8 + er) * 16 + j * 8 + ec];
                        z0 += pp.x; z1 += pp.y;
                    }
                    float d0 = tanhf(z0), d1 = tanhf(z1);
                    float h0 = hreg[rt][j].x + (d0 - hreg[rt][j].x) * itau_s[nl];
                    float h1 = hreg[rt][j].y + (d1 - hreg[rt][j].y) * itau_s[nl + 1];
                    hreg[rt][j] = make_float2(h0, h1);
                    __nv_bfloat16 b0 = __float2bfloat16(h0);
                    __nv_bfloat16 b1 = __float2bfloat16(h1);
                    hhn[(rb + nl) >> 1] = pbf2(h0, h1);
                    hln[(rb + nl) >> 1] = pbf2(h0 - __bfloat162float(b0),
                                               h1 - __bfloat162float(b1));
                    if (t == SEQ - 1)
                        *(float2*)(g_hf[cur ^ 1] + rb + nl) = make_float2(h0, h1);
                }
            }
        }

        ++nbar;
        bar_arrive(gen0 + nbar);
        // overlap: prefetch next xin while waiting
        if (kg == 0) {
            int tp = (t + 1 < SEQ) ? t + 1 : t;
#pragma unroll
            for (int rt = 0; rt < 2; ++rt) {
                int row = m0 + w_mt * 16 + er + rt * 8;
                const float* xp = g_xin + ((size_t)tp * BATCH + row) * HIDDEN + j0;
#pragma unroll
                for (int j = 0; j < 2; ++j)
                    xv[rt][j] = *(const float2*)(xp + w_nh * 16 + j * 8 + ec);
            }
        }
        bar_wait(gen0 + nbar);
        cur ^= 1;
    }
    // cur == 0; final h in g_hf[0]

    // ---- Phase 3: out = h_final @ W_out + b_out (blocks 0..31) ----
    if (blockIdx.x < 32) {
        const int b03 = (blockIdx.x >> 3) * 32;
        const int o0  = (blockIdx.x & 7) * 32;
        float* h_s  = (float*)smem;                  // [32][1024] reuse W region
        float* wo_s = (float*)(smem + OFF_STAGE);    // [64][32]
        for (int qq = tid; qq < 32 * 256; qq += 512) {
            int r = qq >> 8, cq = qq & 255;
            float4 v = __ldcg((const float4*)(g_hf[cur] + (size_t)(b03 + r) * HIDDEN) + cq);
            *(float4*)&h_s[r * HIDDEN + cq * 4] = v;
        }
        const int ty = tid >> 4, tx = tid & 15;
        float2 acc = *(const float2*)(bout + o0 + tx * 2);
        for (int kc = 0; kc < 16; ++kc) {
            __syncthreads();
            {
                int r = tid >> 3, c4 = tid & 7;      // 512 float4 = 64x32 tile
                *(float4*)&wo_s[r * 32 + c4 * 4] =
                    *(const float4*)(Wout + (size_t)(kc * 64 + r) * OUTPUT + o0 + c4 * 4);
            }
            __syncthreads();
#pragma unroll 16
            for (int kk = 0; kk < 64; ++kk) {
                float hvv = h_s[ty * HIDDEN + kc * 64 + kk];
                float2 w = *(const float2*)&wo_s[kk * 32 + tx * 2];
                acc.x += hvv * w.x; acc.y += hvv * w.y;
            }
        }
        *(float2*)(out + (size_t)(b03 + ty) * OUTPUT + o0 + tx * 2) = acc;
    }
}

// ---------------------------------------------------------------------------
// Launch. Inputs: x, W_in, b_in, W_h, b_h, tau, W_out, b_out
// ---------------------------------------------------------------------------
extern "C" void kernel_launch(void* const* d_in, const int* in_sizes, int n_in,
                              void* d_out, int out_size)
{
    const float* x    = (const float*)d_in[0];
    const float* Win  = (const float*)d_in[1];
    const float* bin  = (const float*)d_in[2];
    const float* Wh   = (const float*)d_in[3];
    const float* bhp  = (const float*)d_in[4];
    const float* tau  = (const float*)d_in[5];
    const float* Wout = (const float*)d_in[6];
    const float* bout = (const float*)d_in[7];
    float* out = (float*)d_out;

    cudaFuncSetAttribute(gemm_xin_mma, cudaFuncAttributeMaxDynamicSharedMemorySize, GEMM_SMEM);
    cudaFuncSetAttribute(scan_mma_kernel, cudaFuncAttributeMaxDynamicSharedMemorySize, SCAN_SMEM);

    conv_x_kernel<<<4096, 256>>>(x);
    conv_w_kernel<<<(INPUT * HIDDEN + 255) / 256, 256>>>(Win);

    dim3 gg(HIDDEN / 64, (BATCH * SEQ) / 128);   // 16 x 512
    gemm_xin_mma<<<gg, 256, GEMM_SMEM>>>(bin);

    scan_mma_kernel<<<NBLK, 512, SCAN_SMEM>>>(Wh, bhp, tau, Wout, bout, out);
}

// round 8
// speedup vs baseline: 1.0480x; 1.0480x over previous
#include <cuda_runtime.h>
#include <cuda_bf16.h>
#include <math.h>
#include <stdint.h>

#define BATCH   128
#define SEQ     512
#define INPUT   512
#define HIDDEN  1024
#define OUTPUT  256
#define NBLK    128
#define JW      32
#define MW      32

// ---------------- device scratch (no allocs allowed) ----------------
__device__ float          g_xin[(size_t)SEQ * BATCH * HIDDEN];   // [s][b][h]
__device__ float          g_hf[2][BATCH * HIDDEN];
__device__ __nv_bfloat16  g_hhi[2][BATCH * HIDDEN];
__device__ __nv_bfloat16  g_hlo[2][BATCH * HIDDEN];
__device__ __nv_bfloat16  g_xhi[(size_t)BATCH * SEQ * INPUT];
__device__ __nv_bfloat16  g_xlo[(size_t)BATCH * SEQ * INPUT];
__device__ __nv_bfloat16  g_wThi[HIDDEN * INPUT];
__device__ __nv_bfloat16  g_wTlo[HIDDEN * INPUT];
__device__ unsigned g_arrive[NBLK * 32];    // 128B-strided arrival flags
__device__ unsigned g_bar_gen;

// ---------------- scan smem layout ----------------
#define OFF_WHI    0                 // [kblk16][n32][128B] 64 KB
#define OFF_WLO    65536             // 64 KB
#define OFF_STAGE  131072            // 3 slots x 32 KB (4 kg x (hi4K+lo4K))
#define OFF_RED    OFF_STAGE         // 12 KB reduction scratch (reuses slot 0)
#define OFF_BH     229376
#define OFF_ITAU   229504
#define OFF_GEN0   229632
#define SCAN_SMEM  229696

// ---------------- gemm smem layout ----------------
#define OFF_GA     0
#define OFF_GB     98304
#define OFF_BIN    147456
#define GEMM_SMEM  147968

__device__ __forceinline__ uint32_t smem_u32(const void* p) {
    uint32_t a;
    asm("{ .reg .u64 t; cvta.to.shared.u64 t, %1; cvt.u32.u64 %0, t; }" : "=r"(a) : "l"(p));
    return a;
}
#define CP_COMMIT() asm volatile("cp.async.commit_group;" ::: "memory")
#define CP_WAIT1()  asm volatile("cp.async.wait_group 1;" ::: "memory")
#define CP_WAIT0()  asm volatile("cp.async.wait_group 0;" ::: "memory")

__device__ __forceinline__ void cp16(uint32_t dst, const void* src) {
    asm volatile("cp.async.cg.shared.global [%0], [%1], 16;" :: "r"(dst), "l"(src) : "memory");
}
__device__ __forceinline__ void ldsm4(uint32_t& r0, uint32_t& r1, uint32_t& r2, uint32_t& r3,
                                      uint32_t a) {
    asm volatile("ldmatrix.sync.aligned.m8n8.x4.shared.b16 {%0,%1,%2,%3}, [%4];"
                 : "=r"(r0), "=r"(r1), "=r"(r2), "=r"(r3) : "r"(a));
}
__device__ __forceinline__ void mma16816(float* d, const uint32_t* a, uint32_t b0, uint32_t b1) {
    asm volatile("mma.sync.aligned.m16n8k16.row.col.f32.bf16.bf16.f32 "
                 "{%0,%1,%2,%3}, {%4,%5,%6,%7}, {%8,%9}, {%0,%1,%2,%3};"
                 : "+f"(d[0]), "+f"(d[1]), "+f"(d[2]), "+f"(d[3])
                 : "r"(a[0]), "r"(a[1]), "r"(a[2]), "r"(a[3]), "r"(b0), "r"(b1));
}

// ---- flag-array grid barrier: parallel arrivals, block0 gathers & releases ----
__device__ __forceinline__ void bar_arrive(unsigned target)
{
    __syncthreads();
    if (threadIdx.x == 0) {
        __threadfence();
        atomicExch(&g_arrive[blockIdx.x * 32], target);
    }
}
__device__ __forceinline__ void bar_wait(unsigned target)
{
    if (blockIdx.x == 0) {
        if (threadIdx.x < NBLK) {
            while ((int)(*(volatile unsigned*)&g_arrive[threadIdx.x * 32] - target) < 0) { }
        }
        __syncthreads();
        if (threadIdx.x == 0) {
            __threadfence();
            atomicExch(&g_bar_gen, target);
        }
    }
    if (threadIdx.x == 0) {
        while ((int)(*(volatile unsigned*)&g_bar_gen - target) < 0) { }
        __threadfence();
    }
    __syncthreads();
}

__device__ __forceinline__ uint32_t pbf2(float a, float b) {
    __nv_bfloat162 t = __floats2bfloat162_rn(a, b);
    return *(uint32_t*)&t;
}

// ---------------------------------------------------------------------------
// Conversion kernels: fp32 -> bf16 hi/lo planes
// ---------------------------------------------------------------------------
__global__ __launch_bounds__(256) void conv_x_kernel(const float* __restrict__ x)
{
    const size_t total = (size_t)BATCH * SEQ * INPUT / 2;
    size_t base = (size_t)blockIdx.x * 256 + threadIdx.x;
    size_t stride = (size_t)gridDim.x * 256;
    uint32_t* xhi = (uint32_t*)g_xhi;
    uint32_t* xlo = (uint32_t*)g_xlo;
    for (size_t p = base; p < total; p += stride) {
        float2 v = ((const float2*)x)[p];
        uint32_t hp = pbf2(v.x, v.y);
        __nv_bfloat162 hb = *(__nv_bfloat162*)&hp;
        xhi[p] = hp;
        xlo[p] = pbf2(v.x - __bfloat162float(hb.x), v.y - __bfloat162float(hb.y));
    }
}

__global__ __launch_bounds__(256) void conv_w_kernel(const float* __restrict__ Win)
{
    int idx = blockIdx.x * 256 + threadIdx.x;
    if (idx >= INPUT * HIDDEN) return;
    int k = idx >> 10, n = idx & 1023;
    float w = Win[idx];
    __nv_bfloat16 whi = __float2bfloat16(w);
    g_wThi[(size_t)n * INPUT + k] = whi;
    g_wTlo[(size_t)n * INPUT + k] = __float2bfloat16(w - __bfloat162float(whi));
}

// ---------------------------------------------------------------------------
// Phase 1: xin = x @ W_in + b_in  (bf16x3 mma). Block: M=128, N=64, K=512.
// ---------------------------------------------------------------------------
__device__ __forceinline__ void gstage(uint32_t sb, int kc, int m0, int n0, int tid)
{
    uint32_t abase = sb + OFF_GA + (uint32_t)(kc % 3) * 32768u;
    uint32_t bbase = sb + OFF_GB + (uint32_t)(kc % 3) * 16384u;
#pragma unroll
    for (int u = 0; u < 8; ++u) {
        int g = tid + u * 256;
        int seg = g & 7, row = (g >> 3) & 127, plane = g >> 10;
        const char* src = (const char*)(plane ? g_xlo : g_xhi)
                        + (size_t)(m0 + row) * 1024 + (size_t)kc * 128 + seg * 16;
        uint32_t dst = abase + plane * 16384 + row * 128 + ((seg * 16) ^ ((row & 7) << 4));
        cp16(dst, src);
    }
#pragma unroll
    for (int u = 0; u < 4; ++u) {
        int g = tid + u * 256;
        int seg = g & 7, row = (g >> 3) & 63, plane = g >> 9;
        const char* src = (const char*)(plane ? g_wTlo : g_wThi)
                        + (size_t)(n0 + row) * 1024 + (size_t)kc * 128 + seg * 16;
        uint32_t dst = bbase + plane * 8192 + row * 128 + ((seg * 16) ^ ((row & 7) << 4));
        cp16(dst, src);
    }
}

__global__ __launch_bounds__(256, 1) void gemm_xin_mma(const float* __restrict__ bin)
{
    extern __shared__ __align__(1024) char smem[];
    const uint32_t sb = smem_u32(smem);
    const int tid = threadIdx.x, wid = tid >> 5, lid = tid & 31;
    const int n0 = blockIdx.x * 64, m0 = blockIdx.y * 128;
    const int mq = wid & 3, nh = wid >> 2;
    float* bin_s = (float*)(smem + OFF_BIN);
    if (tid < 16) ((float4*)bin_s)[tid] = ((const float4*)(bin + n0))[tid];

    const int grp = lid >> 3;
    int a_rowl[2];
    a_rowl[0] = mq * 32 + (lid & 7) + ((grp & 1) << 3);
    a_rowl[1] = a_rowl[0] + 16;
    const int a_koff = (grp >> 1) << 4;
    const int b_nr   = nh * 32 + (lid & 7) + ((grp >> 1) << 3);
    const int b_koff = (grp & 1) << 4;
    const uint32_t b_xor = (uint32_t)((b_nr & 7) << 4);

    float acc[2][4][4];
#pragma unroll
    for (int i = 0; i < 2; ++i)
#pragma unroll
        for (int j = 0; j < 4; ++j)
#pragma unroll
            for (int r = 0; r < 4; ++r) acc[i][j][r] = 0.0f;

    gstage(sb, 0, m0, n0, tid); CP_COMMIT();
    gstage(sb, 1, m0, n0, tid); CP_COMMIT();

    for (int kc = 0; kc < 8; ++kc) {
        CP_WAIT1();
        __syncthreads();
        if (kc + 2 < 8) gstage(sb, kc + 2, m0, n0, tid);
        CP_COMMIT();
        const uint32_t abase = sb + OFF_GA + (uint32_t)(kc % 3) * 32768u;
        const uint32_t bbase = sb + OFF_GB + (uint32_t)(kc % 3) * 16384u;
#pragma unroll
        for (int k2 = 0; k2 < 4; ++k2) {
            const uint32_t kb = (uint32_t)(k2 * 32);
            uint32_t ahi[2][4], alo[2][4];
#pragma unroll
            for (int mt = 0; mt < 2; ++mt) {
                uint32_t aa = abase + (uint32_t)(a_rowl[mt] * 128)
                            + ((kb + a_koff) ^ ((a_rowl[mt] & 7) << 4));
                ldsm4(ahi[mt][0], ahi[mt][1], ahi[mt][2], ahi[mt][3], aa);
                ldsm4(alo[mt][0], alo[mt][1], alo[mt][2], alo[mt][3], aa + 16384);
            }
            uint32_t bhi[8], blo[8];
            {
                uint32_t ba = bbase + (uint32_t)(b_nr * 128) + ((kb + b_koff) ^ b_xor);
                ldsm4(bhi[0], bhi[1], bhi[2], bhi[3], ba);
                ldsm4(bhi[4], bhi[5], bhi[6], bhi[7], ba + 2048);
                ldsm4(blo[0], blo[1], blo[2], blo[3], ba + 8192);
                ldsm4(blo[4], blo[5], blo[6], blo[7], ba + 8192 + 2048);
            }
#pragma unroll
            for (int mt = 0; mt < 2; ++mt)
#pragma unroll
                for (int j = 0; j < 4; ++j) {
                    mma16816(acc[mt][j], ahi[mt], bhi[j * 2], bhi[j * 2 + 1]);
                    mma16816(acc[mt][j], alo[mt], bhi[j * 2], bhi[j * 2 + 1]);
                    mma16816(acc[mt][j], ahi[mt], blo[j * 2], blo[j * 2 + 1]);
                }
        }
    }

    const int er = lid >> 2, ec = (lid & 3) * 2;
#pragma unroll
    for (int mt = 0; mt < 2; ++mt)
#pragma unroll
        for (int rt = 0; rt < 2; ++rt) {
            int m = m0 + mq * 32 + mt * 16 + er + rt * 8;
            int b = m >> 9, s = m & 511;
            float* orow = g_xin + ((size_t)s * BATCH + b) * HIDDEN + n0;
#pragma unroll
            for (int j = 0; j < 4; ++j) {
                int nl = nh * 32 + j * 8 + ec;
                float2 v;
                v.x = acc[mt][j][rt * 2 + 0] + bin_s[nl];
                v.y = acc[mt][j][rt * 2 + 1] + bin_s[nl + 1];
                *(float2*)(orow + nl) = v;
            }
        }
}

// ---------------------------------------------------------------------------
// Scan: 128 blocks x 512 threads. 16 warps = 2m x 2n x 4k.
// Slot (32KB): kg in 0..3 at kg*8192: hi [32row][128B] + lo at +4096.
// Iteration i stages chunks {i, 4+i, 8+i, 12+i} (chunk c = kg*4 + i).
// ---------------------------------------------------------------------------
__device__ __forceinline__ void stage_quad(uint32_t sb, const __nv_bfloat16* hi,
                                           const __nv_bfloat16* lo, int i, int m0, int tid)
{
    uint32_t base = sb + OFF_STAGE + (uint32_t)(i % 3) * 32768u;
#pragma unroll
    for (int u = 0; u < 4; ++u) {
        int g = tid + u * 512;                 // seg(8) x row(32) x plane(2) x kg(4)
        int seg = g & 7, row = (g >> 3) & 31, plane = (g >> 8) & 1, kg = g >> 9;
        int c = kg * 4 + i;
        const char* src = (const char*)(plane ? lo : hi)
                        + (size_t)(m0 + row) * 2048 + (size_t)c * 128 + seg * 16;
        uint32_t dst = base + kg * 8192 + plane * 4096 + row * 128
                     + ((seg * 16) ^ ((row & 7) << 4));
        cp16(dst, src);
    }
}

__global__ __launch_bounds__(512, 1) void scan_mma_kernel(
    const float* __restrict__ Wh,  const float* __restrict__ bh,
    const float* __restrict__ tau, const float* __restrict__ Wout,
    const float* __restrict__ bout, float* __restrict__ out)
{
    extern __shared__ __align__(1024) char smem[];
    const uint32_t sb = smem_u32(smem);
    const int tid = threadIdx.x, wid = tid >> 5, lid = tid & 31;
    const int jt = blockIdx.x >> 2, mt_blk = blockIdx.x & 3;
    const int j0 = jt * JW, m0 = mt_blk * MW;
    float* bh_s   = (float*)(smem + OFF_BH);
    float* itau_s = (float*)(smem + OFF_ITAU);
    float* red    = (float*)(smem + OFF_RED);

    if (tid == 0) *(unsigned*)(smem + OFF_GEN0) = *(volatile unsigned*)&g_bar_gen;
    if (tid < JW) {
        bh_s[tid]   = bh[j0 + tid];
        itau_s[tid] = 1.0f / tau[j0 + tid];
    }

    // W slice -> SMEM bf16 hi/lo, [kblk16][n32][128B] swizzled
    for (int idx = tid; idx < 1024 * 8; idx += 512) {
        int k = idx >> 3, nq = idx & 7;
        float4 wv = *(const float4*)(Wh + (size_t)k * HIDDEN + j0 + nq * 4);
        float w[4] = {wv.x, wv.y, wv.z, wv.w};
#pragma unroll
        for (int e = 0; e < 4; ++e) {
            int n = nq * 4 + e;
            uint32_t so = (uint32_t)((k >> 6) * 4096 + n * 128)
                        + (uint32_t)((((k & 63) * 2) ^ ((n & 7) << 4)));
            __nv_bfloat16 whi = __float2bfloat16(w[e]);
            *(__nv_bfloat16*)(smem + OFF_WHI + so) = whi;
            *(__nv_bfloat16*)(smem + OFF_WLO + so) =
                __float2bfloat16(w[e] - __bfloat162float(whi));
        }
    }

    // zero own h plane patch
    for (int idx = tid; idx < MW * JW / 2; idx += 512) {
        int r = idx / (JW / 2), c = idx % (JW / 2);
        size_t o = (size_t)(m0 + r) * HIDDEN + j0 + c * 2;
        *(uint32_t*)(g_hhi[0] + o) = 0u;
        *(uint32_t*)(g_hlo[0] + o) = 0u;
    }
    __syncthreads();
    const unsigned gen0 = *(unsigned*)(smem + OFF_GEN0);

    unsigned nbar = 0;
    ++nbar; bar_arrive(gen0 + nbar); bar_wait(gen0 + nbar);

    // warp roles: 2m x 2n x 4k
    const int w_mt = wid & 1, w_nh = (wid >> 1) & 1, kg = wid >> 2;
    const int grp = lid >> 3;
    const int a_row  = w_mt * 16 + (lid & 7) + ((grp & 1) << 3);
    const int a_koff = (grp >> 1) << 4;
    const uint32_t a_off = (uint32_t)(a_row * 128);
    const uint32_t a_xor = (uint32_t)((a_row & 7) << 4);
    const int b_nr   = w_nh * 16 + (lid & 7) + ((grp >> 1) << 3);
    const int b_koff = (grp & 1) << 4;
    const uint32_t b_xor = (uint32_t)((b_nr & 7) << 4);
    const int er = lid >> 2, ec = (lid & 3) * 2;
    const int q = w_mt * 2 + w_nh;

    // registers: carried h (kg0 only) + prefetched xin
    float2 hreg[2][2], xv[2][2];
#pragma unroll
    for (int rt = 0; rt < 2; ++rt)
#pragma unroll
        for (int j = 0; j < 2; ++j) hreg[rt][j] = make_float2(0.f, 0.f);
    if (kg == 0) {
#pragma unroll
        for (int rt = 0; rt < 2; ++rt) {
            int row = m0 + w_mt * 16 + er + rt * 8;
            const float* xp = g_xin + (size_t)row * HIDDEN + j0;   // t = 0
#pragma unroll
            for (int j = 0; j < 2; ++j)
                xv[rt][j] = *(const float2*)(xp + w_nh * 16 + j * 8 + ec);
        }
    }

    int cur = 0;
    for (int t = 0; t < SEQ; ++t) {
        const __nv_bfloat16* hhi = g_hhi[cur];
        const __nv_bfloat16* hlo = g_hlo[cur];

        float acc[2][4];
#pragma unroll
        for (int j = 0; j < 2; ++j)
#pragma unroll
            for (int r = 0; r < 4; ++r) acc[j][r] = 0.0f;

        stage_quad(sb, hhi, hlo, 0, m0, tid); CP_COMMIT();
        stage_quad(sb, hhi, hlo, 1, m0, tid); CP_COMMIT();

        for (int i = 0; i < 4; ++i) {
            CP_WAIT1();
            __syncthreads();
            if (i + 2 < 4) stage_quad(sb, hhi, hlo, i + 2, m0, tid);
            CP_COMMIT();

            const uint32_t abase = sb + OFF_STAGE + (uint32_t)(i % 3) * 32768u
                                 + (uint32_t)(kg * 8192);
            const int c = kg * 4 + i;
            const uint32_t wbase = sb + OFF_WHI + (uint32_t)(c * 4096);
#pragma unroll
            for (int k2 = 0; k2 < 4; ++k2) {
                const uint32_t kb = (uint32_t)(k2 * 32);
                uint32_t ahi[4], alo[4];
                uint32_t aa = abase + a_off + ((kb + a_koff) ^ a_xor);
                ldsm4(ahi[0], ahi[1], ahi[2], ahi[3], aa);
                ldsm4(alo[0], alo[1], alo[2], alo[3], aa + 4096);
                uint32_t bhi[4], blo[4];
                uint32_t ba = wbase + (uint32_t)(b_nr * 128) + ((kb + b_koff) ^ b_xor);
                ldsm4(bhi[0], bhi[1], bhi[2], bhi[3], ba);
                ldsm4(blo[0], blo[1], blo[2], blo[3], ba + (OFF_WLO - OFF_WHI));
#pragma unroll
                for (int j = 0; j < 2; ++j) {
                    mma16816(acc[j], ahi, bhi[j * 2], bhi[j * 2 + 1]);
                    mma16816(acc[j], alo, bhi[j * 2], bhi[j * 2 + 1]);
                    mma16816(acc[j], ahi, blo[j * 2], blo[j * 2 + 1]);
                }
            }
        }
        CP_WAIT0();
        __syncthreads();                      // all compute on slot 0 done

        // k-reduction: kg 1..3 publish partials into slot-0 scratch
        if (kg != 0) {
#pragma unroll
            for (int rt = 0; rt < 2; ++rt)
#pragma unroll
                for (int j = 0; j < 2; ++j)
                    *(float2*)&red[((kg - 1) * 4 + q) * 256 + (rt * 8 + er) * 16 + j * 8 + ec]
                        = make_float2(acc[j][rt * 2], acc[j][rt * 2 + 1]);
        }
        __syncthreads();

        if (kg == 0) {
            uint32_t* hhn = (uint32_t*)g_hhi[cur ^ 1];
            uint32_t* hln = (uint32_t*)g_hlo[cur ^ 1];
#pragma unroll
            for (int rt = 0; rt < 2; ++rt) {
                int row = m0 + w_mt * 16 + er + rt * 8;
                size_t rb = (size_t)row * HIDDEN + j0;
#pragma unroll
                for (int j = 0; j < 2; ++j) {
                    int nl = w_nh * 16 + j * 8 + ec;
                    float z0 = acc[j][rt * 2 + 0] + xv[rt][j].x + bh_s[nl];
                    float z1 = acc[j][rt * 2 + 1] + xv[rt][j].y + bh_s[nl + 1];
#pragma unroll
                    for (int p = 0; p < 3; ++p) {
                        float2 pp = *(float2*)&red[(p * 4 + q) * 256
                                                   + (rt * 8 + er) * 16 + j * 8 + ec];
                        z0 += pp.x; z1 += pp.y;
                    }
                    float d0 = tanhf(z0), d1 = tanhf(z1);
                    float h0 = hreg[rt][j].x + (d0 - hreg[rt][j].x) * itau_s[nl];
                    float h1 = hreg[rt][j].y + (d1 - hreg[rt][j].y) * itau_s[nl + 1];
                    hreg[rt][j] = make_float2(h0, h1);
                    __nv_bfloat16 b0 = __float2bfloat16(h0);
                    __nv_bfloat16 b1 = __float2bfloat16(h1);
                    hhn[(rb + nl) >> 1] = pbf2(h0, h1);
                    hln[(rb + nl) >> 1] = pbf2(h0 - __bfloat162float(b0),
                                               h1 - __bfloat162float(b1));
                    if (t == SEQ - 1)
                        *(float2*)(g_hf[cur ^ 1] + rb + nl) = make_float2(h0, h1);
                }
            }
        }

        ++nbar;
        bar_arrive(gen0 + nbar);
        // overlap: prefetch next xin while waiting
        if (kg == 0) {
            int tp = (t + 1 < SEQ) ? t + 1 : t;
#pragma unroll
            for (int rt = 0; rt < 2; ++rt) {
                int row = m0 + w_mt * 16 + er + rt * 8;
                const float* xp = g_xin + ((size_t)tp * BATCH + row) * HIDDEN + j0;
#pragma unroll
                for (int j = 0; j < 2; ++j)
                    xv[rt][j] = *(const float2*)(xp + w_nh * 16 + j * 8 + ec);
            }
        }
        bar_wait(gen0 + nbar);
        cur ^= 1;
    }
    // cur == 0; final h in g_hf[0]

    // ---- Phase 3: out = h_final @ W_out + b_out (blocks 0..31) ----
    if (blockIdx.x < 32) {
        const int b03 = (blockIdx.x >> 3) * 32;
        const int o0  = (blockIdx.x & 7) * 32;
        float* h_s  = (float*)smem;                  // [32][1024] reuse W region
        float* wo_s = (float*)(smem + OFF_STAGE);    // [64][32]
        for (int qq = tid; qq < 32 * 256; qq += 512) {
            int r = qq >> 8, cq = qq & 255;
            float4 v = __ldcg((const float4*)(g_hf[cur] + (size_t)(b03 + r) * HIDDEN) + cq);
            *(float4*)&h_s[r * HIDDEN + cq * 4] = v;
        }
        const int ty = tid >> 4, tx = tid & 15;
        float2 acc = *(const float2*)(bout + o0 + tx * 2);
        for (int kc = 0; kc < 16; ++kc) {
            __syncthreads();
            {
                int r = tid >> 3, c4 = tid & 7;      // 512 float4 = 64x32 tile
                *(float4*)&wo_s[r * 32 + c4 * 4] =
                    *(const float4*)(Wout + (size_t)(kc * 64 + r) * OUTPUT + o0 + c4 * 4);
            }
            __syncthreads();
#pragma unroll 16
            for (int kk = 0; kk < 64; ++kk) {
                float hvv = h_s[ty * HIDDEN + kc * 64 + kk];
                float2 w = *(const float2*)&wo_s[kk * 32 + tx * 2];
                acc.x += hvv * w.x; acc.y += hvv * w.y;
            }
        }
        *(float2*)(out + (size_t)(b03 + ty) * OUTPUT + o0 + tx * 2) = acc;
    }
}

// ---------------------------------------------------------------------------
// Launch. Inputs: x, W_in, b_in, W_h, b_h, tau, W_out, b_out
// ---------------------------------------------------------------------------
extern "C" void kernel_launch(void* const* d_in, const int* in_sizes, int n_in,
                              void* d_out, int out_size)
{
    const float* x    = (const float*)d_in[0];
    const float* Win  = (const float*)d_in[1];
    const float* bin  = (const float*)d_in[2];
    const float* Wh   = (const float*)d_in[3];
    const float* bhp  = (const float*)d_in[4];
    const float* tau  = (const float*)d_in[5];
    const float* Wout = (const float*)d_in[6];
    const float* bout = (const float*)d_in[7];
    float* out = (float*)d_out;

    cudaFuncSetAttribute(gemm_xin_mma, cudaFuncAttributeMaxDynamicSharedMemorySize, GEMM_SMEM);
    cudaFuncSetAttribute(scan_mma_kernel, cudaFuncAttributeMaxDynamicSharedMemorySize, SCAN_SMEM);

    conv_x_kernel<<<4096, 256>>>(x);
    conv_w_kernel<<<(INPUT * HIDDEN + 255) / 256, 256>>>(Win);

    dim3 gg(HIDDEN / 64, (BATCH * SEQ) / 128);   // 16 x 512
    gemm_xin_mma<<<gg, 256, GEMM_SMEM>>>(bin);

    scan_mma_kernel<<<NBLK, 512, SCAN_SMEM>>>(Wh, bhp, tau, Wout, bout, out);
}